// round 2
// baseline (speedup 1.0000x reference)
#include <cuda_runtime.h>
#include <math.h>

// ---------------- problem constants ----------------
#define Bg   64
#define NPG  20
#define Hd   512
#define TDd  256
#define NFd  128
#define NLd  6
#define Ad   100
#define Nn   (Bg*NPG)           // 1280 nodes
#define Ee   (Bg*NPG*(NPG-1))   // 24320 edges
#define EINc 2313
#define EPN  (NPG-1)            // 19 edges per src node (consecutive)
#define TWO_PI_F 6.283185307179586f
#define INV_2PI_F 0.15915494309189535f

// ---------------- scratch (device globals; no cudaMalloc allowed) ----------------
__device__ float g_ltl [Bg*9];
__device__ float g_fd  [Ee*3];
__device__ float g_ud  [Ee*3];
__device__ float g_femb[Ee*768];        // 74.7 MB, layer-invariant
__device__ float g_v   [Hd];
__device__ float g_T   [Ad*Hd];
__device__ float g_h   [Nn*Hd];
__device__ float g_hn  [Nn*Hd];
__device__ float g_hsrc[Nn*Hd];
__device__ float g_hdst[Nn*Hd];
__device__ float g_agg [Nn*Hd];
__device__ float g_t1  [Nn*Hd];
__device__ float g_cat [Nn*2*Hd];
__device__ float g_cvec[NLd*Bg*Hd];
__device__ float g_fpre[Ee*Hd];         // 49.8 MB
__device__ float g_e1  [Ee*Hd];
__device__ float g_e2  [Ee*Hd];
__device__ float g_sp  [Bg*Hd];

__device__ __forceinline__ float silu_f(float x) { return x / (1.f + expf(-x)); }

// ---------------- generic SGEMM: C(MxN=512) = A(MxK) @ B(Kx512), ldb = 512 ----------------
// MODE 0: C = acc
// MODE 1: C = silu(acc + bias)
// MODE 2: C += silu(acc + bias)
#define BMt 128
#define BNt 64
#define BKt 16

template<int MODE>
__global__ __launch_bounds__(256) void sgemm_k(
    const float* __restrict__ A, const float* __restrict__ Bm,
    const float* __restrict__ bias, float* __restrict__ C,
    int M, int K)
{
    const int N = 512;
    __shared__ float As[BKt][BMt + 4];
    __shared__ float Bs[BKt][BNt];
    int tid = threadIdx.x;
    int tx = tid & 15, ty = tid >> 4;
    int rowBase = blockIdx.y * BMt;
    int colBase = blockIdx.x * BNt;
    float acc[8][4];
#pragma unroll
    for (int i = 0; i < 8; i++)
#pragma unroll
        for (int j = 0; j < 4; j++) acc[i][j] = 0.f;

    int aRow = tid >> 2;            // 0..63
    int aCol = (tid & 3) << 2;      // 0,4,8,12
    int bRow = tid >> 4;            // 0..15
    int bCol = (tid & 15) << 2;     // 0..60

    for (int k0 = 0; k0 < K; k0 += BKt) {
#pragma unroll
        for (int hh = 0; hh < 2; hh++) {
            int r = aRow + hh * 64;
            int gr = rowBase + r;
            float4 v = make_float4(0.f, 0.f, 0.f, 0.f);
            if (gr < M) v = *(const float4*)(A + (long)gr * K + k0 + aCol);
            As[aCol + 0][r] = v.x; As[aCol + 1][r] = v.y;
            As[aCol + 2][r] = v.z; As[aCol + 3][r] = v.w;
        }
        {
            float4 v = *(const float4*)(Bm + (long)(k0 + bRow) * N + colBase + bCol);
            *(float4*)&Bs[bRow][bCol] = v;
        }
        __syncthreads();
#pragma unroll
        for (int k = 0; k < BKt; k++) {
            float4 a0 = *(const float4*)&As[k][ty * 8];
            float4 a1 = *(const float4*)&As[k][ty * 8 + 4];
            float4 b0 = *(const float4*)&Bs[k][tx * 4];
            float av[8] = {a0.x, a0.y, a0.z, a0.w, a1.x, a1.y, a1.z, a1.w};
            float bv[4] = {b0.x, b0.y, b0.z, b0.w};
#pragma unroll
            for (int i = 0; i < 8; i++)
#pragma unroll
                for (int j = 0; j < 4; j++)
                    acc[i][j] += av[i] * bv[j];
        }
        __syncthreads();
    }

#pragma unroll
    for (int i = 0; i < 8; i++) {
        int gr = rowBase + ty * 8 + i;
        if (gr >= M) continue;
#pragma unroll
        for (int j = 0; j < 4; j++) {
            int gc = colBase + tx * 4 + j;
            float v = acc[i][j];
            if (MODE >= 1) { v += bias[gc]; v = silu_f(v); }
            if (MODE == 2) C[(long)gr * N + gc] += v;
            else           C[(long)gr * N + gc] = v;
        }
    }
}

// ---------------- lattice math: per-graph 3x3 L@L^T ----------------
__global__ void k_lattice(const float* __restrict__ lp, float* __restrict__ ltl)
{
    int b = threadIdx.x;
    if (b >= Bg) return;
    const float LOG_MEANS[3] = {1.575442910194397f, 1.7017393112182617f, 1.9781638383865356f};
    const float LOG_STDS[3]  = {0.24437622725963593f, 0.26526379585266113f, 0.3535512685775757f};
    float len[3], ang[3];
#pragma unroll
    for (int i = 0; i < 3; i++)
        len[i] = expf(lp[b * 6 + i] * LOG_STDS[i] + LOG_MEANS[i]);
#pragma unroll
    for (int i = 0; i < 3; i++) {
        float sgm = 1.f / (1.f + expf(-lp[b * 6 + 3 + i]));
        float deg = 59.9f + 60.2f * sgm;
        ang[i] = deg * 0.017453292519943295f;
    }
    float c0 = cosf(ang[0]), c1 = cosf(ang[1]), c2 = cosf(ang[2]);
    float s0 = sinf(ang[0]), s1 = sinf(ang[1]);
    float val = (c0 * c1 - c2) / (s0 * s1);
    val = fminf(1.f, fmaxf(-1.f, val));
    float gs = acosf(val);
    float L[3][3];
    L[0][0] = len[0] * s1;              L[0][1] = 0.f;                      L[0][2] = len[0] * c1;
    L[1][0] = -len[1] * s0 * cosf(gs);  L[1][1] = len[1] * s0 * sinf(gs);   L[1][2] = len[1] * c0;
    L[2][0] = 0.f;                      L[2][1] = 0.f;                      L[2][2] = len[2];
#pragma unroll
    for (int i = 0; i < 3; i++)
#pragma unroll
        for (int kk = 0; kk < 3; kk++)
            ltl[b * 9 + i * 3 + kk] = L[i][0] * L[kk][0] + L[i][1] * L[kk][1] + L[i][2] * L[kk][2];
}

// ---------------- frac_diff + unit_dots ----------------
__global__ void k_frac(const float* __restrict__ fc, const int* __restrict__ src,
                       const int* __restrict__ dst, const int* __restrict__ e2g,
                       const float* __restrict__ ltl,
                       float* __restrict__ fd, float* __restrict__ ud)
{
    int e = blockIdx.x * blockDim.x + threadIdx.x;
    if (e >= Ee) return;
    int s = src[e], d = dst[e], g = e2g[e];
    float f[3];
#pragma unroll
    for (int i = 0; i < 3; i++) {
        float z = TWO_PI_F * (fc[d * 3 + i] - fc[s * 3 + i]);
        f[i] = atan2f(sinf(z), cosf(z)) * INV_2PI_F;
        fd[e * 3 + i] = f[i];
    }
    float dots[3];
#pragma unroll
    for (int i = 0; i < 3; i++)
        dots[i] = ltl[g * 9 + i * 3 + 0] * f[0] + ltl[g * 9 + i * 3 + 1] * f[1] + ltl[g * 9 + i * 3 + 2] * f[2];
    float nrm = sqrtf(dots[0] * dots[0] + dots[1] * dots[1] + dots[2] * dots[2]) + 1e-12f;
#pragma unroll
    for (int i = 0; i < 3; i++)
        ud[e * 3 + i] = dots[i] / nrm;
}

// ---------------- fourier embedding (layer-invariant) ----------------
__global__ void k_femb(const float* __restrict__ fd, float* __restrict__ femb)
{
    int e = blockIdx.x;
    int j = threadIdx.x;              // 0..383
    int i = j / NFd, f = j % NFd;
    float arg = fd[e * 3 + i] * (TWO_PI_F * (float)f);
    float sn, cs;
    sincosf(arg, &sn, &cs);
    femb[(long)e * 768 + j]       = sn;
    femb[(long)e * 768 + 384 + j] = cs;
}

// ---------------- v[j] = W_time @ W_latent[512:768, :] ----------------
__global__ void k_vtime(const float* __restrict__ wt, const float* __restrict__ wl,
                        float* __restrict__ v)
{
    int j = threadIdx.x;
    float s = 0.f;
    for (int k = 0; k < TDd; k++)
        s += wt[k] * wl[(long)(Hd + k) * Hd + j];
    v[j] = s;
}

// ---------------- h0 = T[atom-1] + t[g]*v ----------------
__global__ void k_h0(const float* __restrict__ T, const int* __restrict__ at,
                     const int* __restrict__ n2g, const float* __restrict__ t,
                     const float* __restrict__ v, float* __restrict__ h)
{
    int n = blockIdx.x, j = threadIdx.x;
    int a = at[n] - 1;
    a = max(0, min(Ad - 1, a));
    h[(long)n * Hd + j] = T[(long)a * Hd + j] + t[n2g[n]] * v[j];
}

// ---------------- per-(layer,graph) constant vector ----------------
// cvec = be1[l] + W_numatom[l][na[b]-1] @ We1_na + lat[b] @ We1_lat
__global__ void k_cvec(const float* __restrict__ We1, const float* __restrict__ Wnum,
                       const float* __restrict__ be1, const int* __restrict__ numat,
                       const float* __restrict__ lat, float* __restrict__ cvec)
{
    int b = blockIdx.x, l = blockIdx.y, j = threadIdx.x;
    int na = numat[b] - 1;
    na = max(0, min(Ad - 1, na));
    const float* wn  = Wnum + ((long)l * Ad + na) * Hd;
    const float* Wna = We1 + ((long)l * EINc + 1801) * Hd;
    const float* Wla = We1 + ((long)l * EINc + 1027) * Hd;
    float s = be1[l * Hd + j];
    for (int k = 0; k < Hd; k++)
        s += wn[k] * Wna[(long)k * Hd + j];
#pragma unroll
    for (int k = 0; k < 6; k++)
        s += lat[b * 6 + k] * Wla[(long)k * Hd + j];
    cvec[((long)l * Bg + b) * Hd + j] = s;
}

// ---------------- layernorm over H=512 ----------------
__global__ void k_ln(const float* __restrict__ x, const float* __restrict__ g,
                     const float* __restrict__ b, float* __restrict__ y)
{
    int r = blockIdx.x, t = threadIdx.x;   // 256 threads
    float v0 = x[(long)r * Hd + t];
    float v1 = x[(long)r * Hd + 256 + t];
    float s = v0 + v1, sq = v0 * v0 + v1 * v1;
#pragma unroll
    for (int o = 16; o > 0; o >>= 1) {
        s  += __shfl_down_sync(0xffffffffu, s, o);
        sq += __shfl_down_sync(0xffffffffu, sq, o);
    }
    __shared__ float ssum[8], ssq[8], smu, srs;
    int w = t >> 5;
    if ((t & 31) == 0) { ssum[w] = s; ssq[w] = sq; }
    __syncthreads();
    if (t == 0) {
        float S = 0.f, Q = 0.f;
#pragma unroll
        for (int i = 0; i < 8; i++) { S += ssum[i]; Q += ssq[i]; }
        float mu = S / (float)Hd;
        float var = Q / (float)Hd - mu * mu;
        smu = mu;
        srs = rsqrtf(var + 1e-5f);
    }
    __syncthreads();
    float mu = smu, rs = srs;
    y[(long)r * Hd + t]       = (v0 - mu) * rs * g[t] + b[t];
    y[(long)r * Hd + 256 + t] = (v1 - mu) * rs * g[256 + t] + b[256 + t];
}

// ---------------- edge pre-activation assembly + silu ----------------
__global__ void k_asm(int l, const float* __restrict__ We1,
                      const int* __restrict__ src, const int* __restrict__ dst,
                      const int* __restrict__ e2g,
                      const float* __restrict__ ud, const float* __restrict__ fpre,
                      const float* __restrict__ hs, const float* __restrict__ hdv,
                      const float* __restrict__ cvec, float* __restrict__ e1)
{
    int e = blockIdx.x, j = threadIdx.x;
    int s = __ldg(&src[e]), d = __ldg(&dst[e]), g = __ldg(&e2g[e]);
    float u0 = __ldg(&ud[e * 3 + 0]), u1 = __ldg(&ud[e * 3 + 1]), u2 = __ldg(&ud[e * 3 + 2]);
    const float* Wud = We1 + (long)l * EINc * Hd;
    float pre = fpre[(long)e * Hd + j]
              + hs[(long)s * Hd + j]
              + hdv[(long)d * Hd + j]
              + cvec[((long)l * Bg + g) * Hd + j]
              + u0 * Wud[j] + u1 * Wud[Hd + j] + u2 * Wud[2 * Hd + j];
    e1[(long)e * Hd + j] = silu_f(pre);
}

// ---------------- segment mean over 19 consecutive edges per src node ----------------
__global__ void k_agg(const float* __restrict__ e2, float* __restrict__ agg)
{
    int n = blockIdx.x, j = threadIdx.x;
    const float* p = e2 + (long)n * EPN * Hd + j;
    float s = 0.f;
#pragma unroll
    for (int k = 0; k < EPN; k++)
        s += p[(long)k * Hd];
    agg[(long)n * Hd + j] = s * (1.f / (float)EPN);
}

// ---------------- concat [hn, agg] ----------------
__global__ void k_cat(const float* __restrict__ hn, const float* __restrict__ agg,
                      float* __restrict__ cat)
{
    int n = blockIdx.x, j = threadIdx.x;
    cat[(long)n * 2 * Hd + j]      = hn[(long)n * Hd + j];
    cat[(long)n * 2 * Hd + Hd + j] = agg[(long)n * Hd + j];
}

// ---------------- pos_v = hnf @ W_coord ----------------
__global__ void k_pos(const float* __restrict__ hnf, const float* __restrict__ wc,
                      float* __restrict__ out)
{
    int n = blockIdx.x;
    int w = threadIdx.x >> 5, lane = threadIdx.x & 31;   // w: 0..2
    float s = 0.f;
    for (int k = lane; k < Hd; k += 32)
        s += hnf[(long)n * Hd + k] * wc[k * 3 + w];
#pragma unroll
    for (int o = 16; o > 0; o >>= 1) s += __shfl_down_sync(0xffffffffu, s, o);
    if (lane == 0) out[n * 3 + w] = s;
}

// ---------------- per-graph sum pool ----------------
__global__ void k_pool(const float* __restrict__ hnf, float* __restrict__ sp)
{
    int b = blockIdx.x, j = threadIdx.x;
    float s = 0.f;
#pragma unroll
    for (int i = 0; i < NPG; i++)
        s += hnf[((long)b * NPG + i) * Hd + j];
    sp[(long)b * Hd + j] = s;
}

// ---------------- cell_v = [mean,sum] @ W_latout + b ----------------
__global__ void k_cell(const float* __restrict__ sp, const float* __restrict__ wl,
                       const float* __restrict__ bl, const int* __restrict__ numat,
                       float* __restrict__ out)
{
    int b = blockIdx.x;
    int w = threadIdx.x >> 5, lane = threadIdx.x & 31;   // w: 0..5
    float inv = 1.f / (float)numat[b];
    float s = 0.f;
    for (int k = lane; k < Hd; k += 32) {
        float v = sp[(long)b * Hd + k];
        s += v * (wl[k * 6 + w] * inv + wl[(Hd + k) * 6 + w]);
    }
#pragma unroll
    for (int o = 16; o > 0; o >>= 1) s += __shfl_down_sync(0xffffffffu, s, o);
    if (lane == 0) out[b * 6 + w] = s + bl[w];
}

// ---------------- launch ----------------
extern "C" void kernel_launch(void* const* d_in, const int* in_sizes, int n_in,
                              void* d_out, int out_size)
{
    // metadata (setup_inputs dict) order:
    const float* t        = (const float*)d_in[0];
    const float* fc       = (const float*)d_in[1];
    const float* lat      = (const float*)d_in[2];
    const int*   at       = (const int*)  d_in[3];
    const int*   numat    = (const int*)  d_in[4];
    const int*   n2g      = (const int*)  d_in[5];
    const int*   ei       = (const int*)  d_in[6];   // (2,E)
    const int*   e2g      = (const int*)  d_in[7];
    const float* W_node   = (const float*)d_in[8];
    const float* W_time   = (const float*)d_in[9];
    const float* W_latent = (const float*)d_in[10];
    const float* ln_g     = (const float*)d_in[11];
    const float* ln_b     = (const float*)d_in[12];
    const float* We1      = (const float*)d_in[13];
    const float* be1      = (const float*)d_in[14];
    const float* We2      = (const float*)d_in[15];
    const float* be2      = (const float*)d_in[16];
    const float* Wn1      = (const float*)d_in[17];
    const float* bn1      = (const float*)d_in[18];
    const float* Wn2      = (const float*)d_in[19];
    const float* bn2      = (const float*)d_in[20];
    const float* Wnum     = (const float*)d_in[21];
    const float* fln_g    = (const float*)d_in[22];
    const float* fln_b    = (const float*)d_in[23];
    const float* W_coord  = (const float*)d_in[24];
    const float* W_latout = (const float*)d_in[25];
    const float* b_latout = (const float*)d_in[26];
    float* out = (float*)d_out;

    const int* src = ei;
    const int* dst = ei + Ee;

    float *ltl, *fd, *ud, *femb, *v, *T, *h, *hn, *hs, *hd, *agg, *t1, *cat, *cvec, *fpre, *e1, *e2, *sp;
    cudaGetSymbolAddress((void**)&ltl,  g_ltl);
    cudaGetSymbolAddress((void**)&fd,   g_fd);
    cudaGetSymbolAddress((void**)&ud,   g_ud);
    cudaGetSymbolAddress((void**)&femb, g_femb);
    cudaGetSymbolAddress((void**)&v,    g_v);
    cudaGetSymbolAddress((void**)&T,    g_T);
    cudaGetSymbolAddress((void**)&h,    g_h);
    cudaGetSymbolAddress((void**)&hn,   g_hn);
    cudaGetSymbolAddress((void**)&hs,   g_hsrc);
    cudaGetSymbolAddress((void**)&hd,   g_hdst);
    cudaGetSymbolAddress((void**)&agg,  g_agg);
    cudaGetSymbolAddress((void**)&t1,   g_t1);
    cudaGetSymbolAddress((void**)&cat,  g_cat);
    cudaGetSymbolAddress((void**)&cvec, g_cvec);
    cudaGetSymbolAddress((void**)&fpre, g_fpre);
    cudaGetSymbolAddress((void**)&e1,   g_e1);
    cudaGetSymbolAddress((void**)&e2,   g_e2);
    cudaGetSymbolAddress((void**)&sp,   g_sp);

    // ---- precompute ----
    k_lattice<<<1, 64>>>(lat, ltl);
    k_frac<<<(Ee + 255) / 256, 256>>>(fc, src, dst, e2g, ltl, fd, ud);
    k_femb<<<Ee, 384>>>(fd, femb);
    k_vtime<<<1, Hd>>>(W_time, W_latent, v);
    sgemm_k<0><<<dim3(8, (Ad + BMt - 1) / BMt), 256>>>(W_node, W_latent, nullptr, T, Ad, Hd);
    k_h0<<<Nn, Hd>>>(T, at, n2g, t, v, h);
    k_cvec<<<dim3(Bg, NLd), Hd>>>(We1, Wnum, be1, numat, lat, cvec);

    dim3 gE(8, Ee / BMt);               // (8, 190)  -- FIXED (was Ee/BMt/8 = 23: only 12% of edges computed)
    dim3 gN(8, Nn / BMt);               // (8, 10)

    for (int l = 0; l < NLd; l++) {
        const float* W1l = We1 + (long)l * EINc * Hd;
        k_ln<<<Nn, 256>>>(h, ln_g + l * Hd, ln_b + l * Hd, hn);
        sgemm_k<0><<<gE, 256>>>(femb, W1l + 1033 * Hd, nullptr, fpre, Ee, 768);
        sgemm_k<0><<<gN, 256>>>(hn, W1l + 3 * Hd, nullptr, hs, Nn, Hd);
        sgemm_k<0><<<gN, 256>>>(hn, W1l + 515 * Hd, nullptr, hd, Nn, Hd);
        k_asm<<<Ee, Hd>>>(l, We1, src, dst, e2g, ud, fpre, hs, hd, cvec, e1);
        sgemm_k<1><<<gE, 256>>>(e1, We2 + (long)l * Hd * Hd, be2 + l * Hd, e2, Ee, Hd);
        k_agg<<<Nn, Hd>>>(e2, agg);
        k_cat<<<Nn, Hd>>>(hn, agg, cat);
        sgemm_k<1><<<gN, 256>>>(cat, Wn1 + (long)l * 2 * Hd * Hd, bn1 + l * Hd, t1, Nn, 2 * Hd);
        sgemm_k<2><<<gN, 256>>>(t1, Wn2 + (long)l * Hd * Hd, bn2 + l * Hd, h, Nn, Hd);
    }

    // ---- head ----
    k_ln<<<Nn, 256>>>(h, fln_g, fln_b, hn);
    k_pos<<<Nn, 96>>>(hn, W_coord, out);
    k_pool<<<Bg, Hd>>>(hn, sp);
    k_cell<<<Bg, 192>>>(sp, W_latout, b_latout, numat, out + Nn * 3);
}

// round 13
// speedup vs baseline: 1.7309x; 1.7309x over previous
#include <cuda_runtime.h>
#include <math.h>
#include <stdint.h>

// ---------------- problem constants ----------------
#define Bg   64
#define NPG  20
#define Hd   512
#define TDd  256
#define NFd  128
#define NLd  6
#define Ad   100
#define Nn   (Bg*NPG)           // 1280 nodes
#define Ee   (Bg*NPG*(NPG-1))   // 24320 edges
#define EINc 2313
#define EPN  (NPG-1)            // 19 edges per src node (consecutive)
#define TWO_PI_F 6.283185307179586f
#define INV_2PI_F 0.15915494309189535f
#define WT_PER_L 1966080        // transposed-weight floats per layer

// ---------------- scratch (device globals; no cudaMalloc allowed) ----------------
__device__ float g_ltl [Bg*9];
__device__ float g_fd  [Ee*3];
__device__ float g_ud  [Ee*3];
__device__ float g_femb[Ee*768];        // 74.7 MB, layer-invariant
__device__ float g_v   [Hd];
__device__ float g_T   [Ad*Hd];
__device__ float g_h   [Nn*Hd];
__device__ float g_hn  [Nn*Hd];
__device__ float g_hsrc[Nn*Hd];
__device__ float g_hdst[Nn*Hd];
__device__ float g_t1  [Nn*Hd];
__device__ float g_cat [Nn*2*Hd];
__device__ float g_cvec[NLd*Bg*Hd];
__device__ float g_fpre[Ee*Hd];         // 49.8 MB
__device__ float g_e1  [Ee*Hd];
__device__ float g_e2  [Ee*Hd];
__device__ float g_sp  [Bg*Hd];
__device__ float g_wt  [NLd*WT_PER_L];  // transposed weights (512/… x K), 47 MB

__device__ __forceinline__ float silu_f(float x) { return x / (1.f + expf(-x)); }

__device__ __forceinline__ uint32_t f2tf32(float x) {
    uint32_t r; asm("cvt.rna.tf32.f32 %0, %1;" : "=r"(r) : "f"(x)); return r;
}

// mma.sync m16n8k8 tf32 (HMMA; valid on base sm_103 target, unlike tcgen05)
__device__ __forceinline__ void mma_tf32(float c[4],
                                         uint32_t a0, uint32_t a1, uint32_t a2, uint32_t a3,
                                         uint32_t b0, uint32_t b1) {
    asm volatile("mma.sync.aligned.m16n8k8.row.col.f32.tf32.tf32.f32 "
        "{%0,%1,%2,%3}, {%4,%5,%6,%7}, {%8,%9}, {%0,%1,%2,%3};"
        : "+f"(c[0]), "+f"(c[1]), "+f"(c[2]), "+f"(c[3])
        : "r"(a0), "r"(a1), "r"(a2), "r"(a3), "r"(b0), "r"(b1));
}

// ---------------- hmma_gemm: C(Mx512) = A(MxK) @ Bt(512,K)^T, tf32 mma.sync ----------------
// MODE 0: C = acc ; MODE 1: C = silu(acc + bias) ; MODE 2: C += silu(acc + bias)
#define BMh 128
#define BNh 64
#define BKh 32
#define SAS 36   // smem word stride: (gid*36 + tig) % 32 covers 32 banks -> conflict-free

template<int MODE>
__global__ __launch_bounds__(256) void hmma_gemm(
    const float* __restrict__ A, const float* __restrict__ Bt,
    const float* __restrict__ bias, float* __restrict__ C,
    int M, int K)
{
    __shared__ uint32_t As[BMh * SAS];   // 18432 B
    __shared__ uint32_t Bs[BNh * SAS];   //  9216 B
    int tid = threadIdx.x;
    int wid = tid >> 5, lane = tid & 31;
    int warpM = wid & 3, warpN = wid >> 2;          // 4 x 2 warp grid
    int gid = lane >> 2, tig = lane & 3;            // octet row, thread-in-group
    int rowBase = blockIdx.y * BMh, colBase = blockIdx.x * BNh;

    float acc[2][4][4];
#pragma unroll
    for (int mt = 0; mt < 2; mt++)
#pragma unroll
        for (int nt = 0; nt < 4; nt++)
#pragma unroll
            for (int i = 0; i < 4; i++) acc[mt][nt][i] = 0.f;

    for (int k0 = 0; k0 < K; k0 += BKh) {
        {   // A tile: 128 rows x 32 cols; 2 threads/row, 16 floats each
            int r = tid >> 1, c0 = (tid & 1) * 16;
            const float4* sp = (const float4*)(A + (long)(rowBase + r) * K + k0 + c0);
            uint32_t* dp = As + r * SAS + c0;
#pragma unroll
            for (int i = 0; i < 4; i++) {
                float4 v = sp[i];
                dp[i * 4 + 0] = f2tf32(v.x); dp[i * 4 + 1] = f2tf32(v.y);
                dp[i * 4 + 2] = f2tf32(v.z); dp[i * 4 + 3] = f2tf32(v.w);
            }
        }
        {   // B tile: 64 rows x 32 cols; 4 threads/row, 8 floats each
            int r = tid >> 2, c0 = (tid & 3) * 8;
            const float4* sp = (const float4*)(Bt + (long)(colBase + r) * K + k0 + c0);
            uint32_t* dp = Bs + r * SAS + c0;
#pragma unroll
            for (int i = 0; i < 2; i++) {
                float4 v = sp[i];
                dp[i * 4 + 0] = f2tf32(v.x); dp[i * 4 + 1] = f2tf32(v.y);
                dp[i * 4 + 2] = f2tf32(v.z); dp[i * 4 + 3] = f2tf32(v.w);
            }
        }
        __syncthreads();
#pragma unroll
        for (int ks = 0; ks < BKh; ks += 8) {
            uint32_t a[2][4];
#pragma unroll
            for (int mt = 0; mt < 2; mt++) {
                int mrow = warpM * 32 + mt * 16;
                a[mt][0] = As[(mrow + gid)     * SAS + ks + tig];
                a[mt][1] = As[(mrow + gid + 8) * SAS + ks + tig];
                a[mt][2] = As[(mrow + gid)     * SAS + ks + tig + 4];
                a[mt][3] = As[(mrow + gid + 8) * SAS + ks + tig + 4];
            }
#pragma unroll
            for (int nt = 0; nt < 4; nt++) {
                int ncol = warpN * 32 + nt * 8;
                uint32_t b0 = Bs[(ncol + gid) * SAS + ks + tig];
                uint32_t b1 = Bs[(ncol + gid) * SAS + ks + tig + 4];
#pragma unroll
                for (int mt = 0; mt < 2; mt++)
                    mma_tf32(acc[mt][nt], a[mt][0], a[mt][1], a[mt][2], a[mt][3], b0, b1);
            }
        }
        __syncthreads();
    }

    // epilogue: c0:(r,c) c1:(r,c+1) c2:(r+8,c) c3:(r+8,c+1), r=base+gid, c=base+2*tig
#pragma unroll
    for (int mt = 0; mt < 2; mt++) {
#pragma unroll
        for (int nt = 0; nt < 4; nt++) {
            int row0 = rowBase + warpM * 32 + mt * 16 + gid;
            int col0 = colBase + warpN * 32 + nt * 8 + 2 * tig;
#pragma unroll
            for (int i = 0; i < 4; i++) {
                int row = row0 + (i >> 1) * 8;
                int col = col0 + (i & 1);
                float v = acc[mt][nt][i];
                if (MODE >= 1) { v += bias[col]; v = silu_f(v); }
                float* cp = C + (long)row * 512 + col;
                if (MODE == 2) *cp += v; else *cp = v;
            }
        }
    }
}

// ---------------- weight transpose: in (K,512) -> out (512,K) ----------------
__global__ void k_tr(const float* __restrict__ in, float* __restrict__ out, int K)
{
    __shared__ float t[32][33];
    int kb = blockIdx.y * 32, nb = blockIdx.x * 32;
    int tx = threadIdx.x, ty = threadIdx.y;   // 32 x 8
#pragma unroll
    for (int j = 0; j < 32; j += 8)
        t[ty + j][tx] = in[(long)(kb + ty + j) * 512 + nb + tx];
    __syncthreads();
#pragma unroll
    for (int j = 0; j < 32; j += 8)
        out[(long)(nb + ty + j) * K + kb + tx] = t[tx][ty + j];
}

// ---------------- fp32 SGEMM kept for the tiny T = W_node @ W_latent[:512] ----------------
#define BMt 128
#define BNt 64
#define BKt 16
template<int MODE>
__global__ __launch_bounds__(256) void sgemm_k(
    const float* __restrict__ A, const float* __restrict__ Bm,
    const float* __restrict__ bias, float* __restrict__ C,
    int M, int K)
{
    const int N = 512;
    __shared__ float As[BKt][BMt + 4];
    __shared__ float Bs[BKt][BNt];
    int tid = threadIdx.x;
    int tx = tid & 15, ty = tid >> 4;
    int rowBase = blockIdx.y * BMt;
    int colBase = blockIdx.x * BNt;
    float acc[8][4];
#pragma unroll
    for (int i = 0; i < 8; i++)
#pragma unroll
        for (int j = 0; j < 4; j++) acc[i][j] = 0.f;
    int aRow = tid >> 2, aCol = (tid & 3) << 2;
    int bRow = tid >> 4, bCol = (tid & 15) << 2;
    for (int k0 = 0; k0 < K; k0 += BKt) {
#pragma unroll
        for (int hh = 0; hh < 2; hh++) {
            int r = aRow + hh * 64;
            int gr = rowBase + r;
            float4 v = make_float4(0.f, 0.f, 0.f, 0.f);
            if (gr < M) v = *(const float4*)(A + (long)gr * K + k0 + aCol);
            As[aCol + 0][r] = v.x; As[aCol + 1][r] = v.y;
            As[aCol + 2][r] = v.z; As[aCol + 3][r] = v.w;
        }
        {
            float4 v = *(const float4*)(Bm + (long)(k0 + bRow) * N + colBase + bCol);
            *(float4*)&Bs[bRow][bCol] = v;
        }
        __syncthreads();
#pragma unroll
        for (int k = 0; k < BKt; k++) {
            float4 a0 = *(const float4*)&As[k][ty * 8];
            float4 a1 = *(const float4*)&As[k][ty * 8 + 4];
            float4 b0 = *(const float4*)&Bs[k][tx * 4];
            float av[8] = {a0.x, a0.y, a0.z, a0.w, a1.x, a1.y, a1.z, a1.w};
            float bv[4] = {b0.x, b0.y, b0.z, b0.w};
#pragma unroll
            for (int i = 0; i < 8; i++)
#pragma unroll
                for (int j = 0; j < 4; j++)
                    acc[i][j] += av[i] * bv[j];
        }
        __syncthreads();
    }
#pragma unroll
    for (int i = 0; i < 8; i++) {
        int gr = rowBase + ty * 8 + i;
        if (gr >= M) continue;
#pragma unroll
        for (int j = 0; j < 4; j++) {
            int gc = colBase + tx * 4 + j;
            float v = acc[i][j];
            if (MODE >= 1) { v += bias[gc]; v = silu_f(v); }
            if (MODE == 2) C[(long)gr * N + gc] += v;
            else           C[(long)gr * N + gc] = v;
        }
    }
}

// ---------------- lattice math ----------------
__global__ void k_lattice(const float* __restrict__ lp, float* __restrict__ ltl)
{
    int b = threadIdx.x;
    if (b >= Bg) return;
    const float LOG_MEANS[3] = {1.575442910194397f, 1.7017393112182617f, 1.9781638383865356f};
    const float LOG_STDS[3]  = {0.24437622725963593f, 0.26526379585266113f, 0.3535512685775757f};
    float len[3], ang[3];
#pragma unroll
    for (int i = 0; i < 3; i++)
        len[i] = expf(lp[b * 6 + i] * LOG_STDS[i] + LOG_MEANS[i]);
#pragma unroll
    for (int i = 0; i < 3; i++) {
        float sgm = 1.f / (1.f + expf(-lp[b * 6 + 3 + i]));
        float deg = 59.9f + 60.2f * sgm;
        ang[i] = deg * 0.017453292519943295f;
    }
    float c0 = cosf(ang[0]), c1 = cosf(ang[1]), c2 = cosf(ang[2]);
    float s0 = sinf(ang[0]), s1 = sinf(ang[1]);
    float val = (c0 * c1 - c2) / (s0 * s1);
    val = fminf(1.f, fmaxf(-1.f, val));
    float gs = acosf(val);
    float L[3][3];
    L[0][0] = len[0] * s1;              L[0][1] = 0.f;                      L[0][2] = len[0] * c1;
    L[1][0] = -len[1] * s0 * cosf(gs);  L[1][1] = len[1] * s0 * sinf(gs);   L[1][2] = len[1] * c0;
    L[2][0] = 0.f;                      L[2][1] = 0.f;                      L[2][2] = len[2];
#pragma unroll
    for (int i = 0; i < 3; i++)
#pragma unroll
        for (int kk = 0; kk < 3; kk++)
            ltl[b * 9 + i * 3 + kk] = L[i][0] * L[kk][0] + L[i][1] * L[kk][1] + L[i][2] * L[kk][2];
}

// ---------------- frac_diff + unit_dots ----------------
__global__ void k_frac(const float* __restrict__ fc, const int* __restrict__ src,
                       const int* __restrict__ dst, const int* __restrict__ e2g,
                       const float* __restrict__ ltl,
                       float* __restrict__ fd, float* __restrict__ ud)
{
    int e = blockIdx.x * blockDim.x + threadIdx.x;
    if (e >= Ee) return;
    int s = src[e], d = dst[e], g = e2g[e];
    float f[3];
#pragma unroll
    for (int i = 0; i < 3; i++) {
        float z = TWO_PI_F * (fc[d * 3 + i] - fc[s * 3 + i]);
        f[i] = atan2f(sinf(z), cosf(z)) * INV_2PI_F;
        fd[e * 3 + i] = f[i];
    }
    float dots[3];
#pragma unroll
    for (int i = 0; i < 3; i++)
        dots[i] = ltl[g * 9 + i * 3 + 0] * f[0] + ltl[g * 9 + i * 3 + 1] * f[1] + ltl[g * 9 + i * 3 + 2] * f[2];
    float nrm = sqrtf(dots[0] * dots[0] + dots[1] * dots[1] + dots[2] * dots[2]) + 1e-12f;
#pragma unroll
    for (int i = 0; i < 3; i++)
        ud[e * 3 + i] = dots[i] / nrm;
}

// ---------------- fourier embedding (layer-invariant) ----------------
__global__ void k_femb(const float* __restrict__ fd, float* __restrict__ femb)
{
    int e = blockIdx.x;
    int j = threadIdx.x;              // 0..383
    int i = j / NFd, f = j % NFd;
    float arg = fd[e * 3 + i] * (TWO_PI_F * (float)f);
    float sn, cs;
    sincosf(arg, &sn, &cs);
    femb[(long)e * 768 + j]       = sn;
    femb[(long)e * 768 + 384 + j] = cs;
}

// ---------------- v[j] = W_time @ W_latent[512:768, :] ----------------
__global__ void k_vtime(const float* __restrict__ wt, const float* __restrict__ wl,
                        float* __restrict__ v)
{
    int j = threadIdx.x;
    float s = 0.f;
    for (int k = 0; k < TDd; k++)
        s += wt[k] * wl[(long)(Hd + k) * Hd + j];
    v[j] = s;
}

// ---------------- h0 = T[atom-1] + t[g]*v ----------------
__global__ void k_h0(const float* __restrict__ T, const int* __restrict__ at,
                     const int* __restrict__ n2g, const float* __restrict__ t,
                     const float* __restrict__ v, float* __restrict__ h)
{
    int n = blockIdx.x, j = threadIdx.x;
    int a = at[n] - 1;
    a = max(0, min(Ad - 1, a));
    h[(long)n * Hd + j] = T[(long)a * Hd + j] + t[n2g[n]] * v[j];
}

// ---------------- per-(layer,graph) constant vector ----------------
__global__ void k_cvec(const float* __restrict__ We1, const float* __restrict__ Wnum,
                       const float* __restrict__ be1, const int* __restrict__ numat,
                       const float* __restrict__ lat, float* __restrict__ cvec)
{
    int b = blockIdx.x, l = blockIdx.y, j = threadIdx.x;
    int na = numat[b] - 1;
    na = max(0, min(Ad - 1, na));
    const float* wn  = Wnum + ((long)l * Ad + na) * Hd;
    const float* Wna = We1 + ((long)l * EINc + 1801) * Hd;
    const float* Wla = We1 + ((long)l * EINc + 1027) * Hd;
    float s = be1[l * Hd + j];
    for (int k = 0; k < Hd; k++)
        s += wn[k] * Wna[(long)k * Hd + j];
#pragma unroll
    for (int k = 0; k < 6; k++)
        s += lat[b * 6 + k] * Wla[(long)k * Hd + j];
    cvec[((long)l * Bg + b) * Hd + j] = s;
}

// ---------------- layernorm over H=512 ----------------
__global__ void k_ln(const float* __restrict__ x, const float* __restrict__ g,
                     const float* __restrict__ b, float* __restrict__ y)
{
    int r = blockIdx.x, t = threadIdx.x;   // 256 threads
    float v0 = x[(long)r * Hd + t];
    float v1 = x[(long)r * Hd + 256 + t];
    float s = v0 + v1, sq = v0 * v0 + v1 * v1;
#pragma unroll
    for (int o = 16; o > 0; o >>= 1) {
        s  += __shfl_down_sync(0xffffffffu, s, o);
        sq += __shfl_down_sync(0xffffffffu, sq, o);
    }
    __shared__ float ssum[8], ssq[8], smu, srs;
    int w = t >> 5;
    if ((t & 31) == 0) { ssum[w] = s; ssq[w] = sq; }
    __syncthreads();
    if (t == 0) {
        float S = 0.f, Q = 0.f;
#pragma unroll
        for (int i = 0; i < 8; i++) { S += ssum[i]; Q += ssq[i]; }
        float mu = S / (float)Hd;
        float var = Q / (float)Hd - mu * mu;
        smu = mu;
        srs = rsqrtf(var + 1e-5f);
    }
    __syncthreads();
    float mu = smu, rs = srs;
    y[(long)r * Hd + t]       = (v0 - mu) * rs * g[t] + b[t];
    y[(long)r * Hd + 256 + t] = (v1 - mu) * rs * g[256 + t] + b[256 + t];
}

// ---------------- edge pre-activation assembly + silu ----------------
__global__ void k_asm(int l, const float* __restrict__ We1,
                      const int* __restrict__ src, const int* __restrict__ dst,
                      const int* __restrict__ e2g,
                      const float* __restrict__ ud, const float* __restrict__ fpre,
                      const float* __restrict__ hs, const float* __restrict__ hdv,
                      const float* __restrict__ cvec, float* __restrict__ e1)
{
    int e = blockIdx.x, j = threadIdx.x;
    int s = __ldg(&src[e]), d = __ldg(&dst[e]), g = __ldg(&e2g[e]);
    float u0 = __ldg(&ud[e * 3 + 0]), u1 = __ldg(&ud[e * 3 + 1]), u2 = __ldg(&ud[e * 3 + 2]);
    const float* Wud = We1 + (long)l * EINc * Hd;
    float pre = fpre[(long)e * Hd + j]
              + hs[(long)s * Hd + j]
              + hdv[(long)d * Hd + j]
              + cvec[((long)l * Bg + g) * Hd + j]
              + u0 * Wud[j] + u1 * Wud[Hd + j] + u2 * Wud[2 * Hd + j];
    e1[(long)e * Hd + j] = silu_f(pre);
}

// ---------------- fused: segment mean over 19 consecutive edges + concat [hn, agg] ----------------
__global__ void k_aggcat(const float* __restrict__ e2, const float* __restrict__ hn,
                         float* __restrict__ cat)
{
    int n = blockIdx.x, j = threadIdx.x;
    const float* p = e2 + (long)n * EPN * Hd + j;
    float s = 0.f;
#pragma unroll
    for (int k = 0; k < EPN; k++)
        s += p[(long)k * Hd];
    cat[(long)n * 2 * Hd + j]      = hn[(long)n * Hd + j];
    cat[(long)n * 2 * Hd + Hd + j] = s * (1.f / (float)EPN);
}

// ---------------- pos_v = hnf @ W_coord ----------------
__global__ void k_pos(const float* __restrict__ hnf, const float* __restrict__ wc,
                      float* __restrict__ out)
{
    int n = blockIdx.x;
    int w = threadIdx.x >> 5, lane = threadIdx.x & 31;   // w: 0..2
    float s = 0.f;
    for (int k = lane; k < Hd; k += 32)
        s += hnf[(long)n * Hd + k] * wc[k * 3 + w];
#pragma unroll
    for (int o = 16; o > 0; o >>= 1) s += __shfl_down_sync(0xffffffffu, s, o);
    if (lane == 0) out[n * 3 + w] = s;
}

// ---------------- per-graph sum pool ----------------
__global__ void k_pool(const float* __restrict__ hnf, float* __restrict__ sp)
{
    int b = blockIdx.x, j = threadIdx.x;
    float s = 0.f;
#pragma unroll
    for (int i = 0; i < NPG; i++)
        s += hnf[((long)b * NPG + i) * Hd + j];
    sp[(long)b * Hd + j] = s;
}

// ---------------- cell_v = [mean,sum] @ W_latout + b ----------------
__global__ void k_cell(const float* __restrict__ sp, const float* __restrict__ wl,
                       const float* __restrict__ bl, const int* __restrict__ numat,
                       float* __restrict__ out)
{
    int b = blockIdx.x;
    int w = threadIdx.x >> 5, lane = threadIdx.x & 31;   // w: 0..5
    float inv = 1.f / (float)numat[b];
    float s = 0.f;
    for (int k = lane; k < Hd; k += 32) {
        float v = sp[(long)b * Hd + k];
        s += v * (wl[k * 6 + w] * inv + wl[(Hd + k) * 6 + w]);
    }
#pragma unroll
    for (int o = 16; o > 0; o >>= 1) s += __shfl_down_sync(0xffffffffu, s, o);
    if (lane == 0) out[b * 6 + w] = s + bl[w];
}

// ---------------- launch ----------------
extern "C" void kernel_launch(void* const* d_in, const int* in_sizes, int n_in,
                              void* d_out, int out_size)
{
    const float* t        = (const float*)d_in[0];
    const float* fc       = (const float*)d_in[1];
    const float* lat      = (const float*)d_in[2];
    const int*   at       = (const int*)  d_in[3];
    const int*   numat    = (const int*)  d_in[4];
    const int*   n2g      = (const int*)  d_in[5];
    const int*   ei       = (const int*)  d_in[6];   // (2,E)
    const int*   e2g      = (const int*)  d_in[7];
    const float* W_node   = (const float*)d_in[8];
    const float* W_time   = (const float*)d_in[9];
    const float* W_latent = (const float*)d_in[10];
    const float* ln_g     = (const float*)d_in[11];
    const float* ln_b     = (const float*)d_in[12];
    const float* We1      = (const float*)d_in[13];
    const float* be1      = (const float*)d_in[14];
    const float* We2      = (const float*)d_in[15];
    const float* be2      = (const float*)d_in[16];
    const float* Wn1      = (const float*)d_in[17];
    const float* bn1      = (const float*)d_in[18];
    const float* Wn2      = (const float*)d_in[19];
    const float* bn2      = (const float*)d_in[20];
    const float* Wnum     = (const float*)d_in[21];
    const float* fln_g    = (const float*)d_in[22];
    const float* fln_b    = (const float*)d_in[23];
    const float* W_coord  = (const float*)d_in[24];
    const float* W_latout = (const float*)d_in[25];
    const float* b_latout = (const float*)d_in[26];
    float* out = (float*)d_out;

    const int* src = ei;
    const int* dst = ei + Ee;

    float *ltl, *fd, *ud, *femb, *v, *T, *h, *hn, *hs, *hd, *t1, *cat, *cvec, *fpre, *e1, *e2, *sp, *wtb;
    cudaGetSymbolAddress((void**)&ltl,  g_ltl);
    cudaGetSymbolAddress((void**)&fd,   g_fd);
    cudaGetSymbolAddress((void**)&ud,   g_ud);
    cudaGetSymbolAddress((void**)&femb, g_femb);
    cudaGetSymbolAddress((void**)&v,    g_v);
    cudaGetSymbolAddress((void**)&T,    g_T);
    cudaGetSymbolAddress((void**)&h,    g_h);
    cudaGetSymbolAddress((void**)&hn,   g_hn);
    cudaGetSymbolAddress((void**)&hs,   g_hsrc);
    cudaGetSymbolAddress((void**)&hd,   g_hdst);
    cudaGetSymbolAddress((void**)&t1,   g_t1);
    cudaGetSymbolAddress((void**)&cat,  g_cat);
    cudaGetSymbolAddress((void**)&cvec, g_cvec);
    cudaGetSymbolAddress((void**)&fpre, g_fpre);
    cudaGetSymbolAddress((void**)&e1,   g_e1);
    cudaGetSymbolAddress((void**)&e2,   g_e2);
    cudaGetSymbolAddress((void**)&sp,   g_sp);
    cudaGetSymbolAddress((void**)&wtb,  g_wt);

    // ---- transpose weights into (512, K) layouts ----
    dim3 trb(32, 8);
    for (int l = 0; l < NLd; l++) {
        float* w = wtb + (long)l * WT_PER_L;
        k_tr<<<dim3(16, 16), trb>>>(We1 + ((long)l * EINc + 3)    * Hd, w + 0,       512);
        k_tr<<<dim3(16, 16), trb>>>(We1 + ((long)l * EINc + 515)  * Hd, w + 262144,  512);
        k_tr<<<dim3(16, 24), trb>>>(We1 + ((long)l * EINc + 1033) * Hd, w + 524288,  768);
        k_tr<<<dim3(16, 16), trb>>>(We2 + (long)l * Hd * Hd,            w + 917504,  512);
        k_tr<<<dim3(16, 32), trb>>>(Wn1 + (long)l * 2 * Hd * Hd,        w + 1179648, 1024);
        k_tr<<<dim3(16, 16), trb>>>(Wn2 + (long)l * Hd * Hd,            w + 1703936, 512);
    }

    // ---- precompute ----
    k_lattice<<<1, 64>>>(lat, ltl);
    k_frac<<<(Ee + 255) / 256, 256>>>(fc, src, dst, e2g, ltl, fd, ud);
    k_femb<<<Ee, 384>>>(fd, femb);
    k_vtime<<<1, Hd>>>(W_time, W_latent, v);
    sgemm_k<0><<<dim3(8, 1), 256>>>(W_node, W_latent, nullptr, T, Ad, Hd);
    k_h0<<<Nn, Hd>>>(T, at, n2g, t, v, h);
    k_cvec<<<dim3(Bg, NLd), Hd>>>(We1, Wnum, be1, numat, lat, cvec);

    dim3 gE(8, Ee / 128);   // (8, 190), BN=64 tiles over N=512
    dim3 gN(8, Nn / 128);   // (8, 10)

    for (int l = 0; l < NLd; l++) {
        const float* w = wtb + (long)l * WT_PER_L;
        k_ln<<<Nn, 256>>>(h, ln_g + l * Hd, ln_b + l * Hd, hn);
        hmma_gemm<0><<<gE, 256>>>(femb, w + 524288,  nullptr,      fpre, Ee, 768);
        hmma_gemm<0><<<gN, 256>>>(hn,   w + 0,       nullptr,      hs,   Nn, 512);
        hmma_gemm<0><<<gN, 256>>>(hn,   w + 262144,  nullptr,      hd,   Nn, 512);
        k_asm<<<Ee, Hd>>>(l, We1, src, dst, e2g, ud, fpre, hs, hd, cvec, e1);
        hmma_gemm<1><<<gE, 256>>>(e1,   w + 917504,  be2 + l * Hd, e2,   Ee, 512);
        k_aggcat<<<Nn, Hd>>>(e2, hn, cat);
        hmma_gemm<1><<<gN, 256>>>(cat,  w + 1179648, bn1 + l * Hd, t1,   Nn, 1024);
        hmma_gemm<2><<<gN, 256>>>(t1,   w + 1703936, bn2 + l * Hd, h,    Nn, 512);
    }

    // ---- head ----
    k_ln<<<Nn, 256>>>(h, fln_g, fln_b, hn);
    k_pos<<<Nn, 96>>>(hn, W_coord, out);
    k_pool<<<Bg, Hd>>>(hn, sp);
    k_cell<<<Bg, 192>>>(sp, W_latout, b_latout, numat, out + Nn * 3);
}